// round 12
// baseline (speedup 1.0000x reference)
#include <cuda_runtime.h>
#include <cuda_bf16.h>

#define HDIM 16
#define UDIM 7
#define HID  64
#define XDIM 23
#define CHUNK 512            // power of 2 (shift/mask indexing)
#define NBUF  3
#define NTHREADS 96

__device__ __forceinline__ unsigned smem_u32(const void* p) {
    return (unsigned)__cvta_generic_to_shared(p);
}
__device__ __forceinline__ void cp16(unsigned dst, const void* src) {
    asm volatile("cp.async.cg.shared.global [%0], [%1], 16;" :: "r"(dst), "l"(src));
}
__device__ __forceinline__ void cp4(unsigned dst, const void* src) {
    asm volatile("cp.async.ca.shared.global [%0], [%1], 4;" :: "r"(dst), "l"(src));
}
__device__ __forceinline__ void cp_commit() {
    asm volatile("cp.async.commit_group;" ::: "memory");
}
__device__ __forceinline__ void cp_wait1() {
    asm volatile("cp.async.wait_group 1;" ::: "memory");
}
__device__ __forceinline__ void cp_wait2() {
    asm volatile("cp.async.wait_group 2;" ::: "memory");
}

// accurate tanh: (e^{2x}-1)/(e^{2x}+1), clamped to avoid inf/inf
__device__ __forceinline__ float ftanh(float x) {
    x = fminf(fmaxf(x, -15.0f), 15.0f);
    float e = __expf(2.0f * x);
    return __fdividef(e - 1.0f, e + 1.0f);
}

// 64-wide dot: 64 register weights x 64 floats in 16B-aligned smem (broadcast reads)
__device__ __forceinline__ float dot64(const float* __restrict__ wr,
                                       const float* __restrict__ zs, float init) {
    const float4* zp = (const float4*)zs;
    float a0 = init, a1 = 0.0f, a2 = 0.0f, a3 = 0.0f;
    #pragma unroll
    for (int j = 0; j < 16; j++) {
        float4 v = zp[j];
        a0 = fmaf(wr[4 * j + 0], v.x, a0);
        a1 = fmaf(wr[4 * j + 1], v.y, a1);
        a2 = fmaf(wr[4 * j + 2], v.z, a2);
        a3 = fmaf(wr[4 * j + 3], v.w, a3);
    }
    return (a0 + a1) + (a2 + a3);
}

__global__ void __launch_bounds__(NTHREADS, 1) node_scan_kernel(
    const float* __restrict__ U,
    const float* __restrict__ W1, const float* __restrict__ b1,
    const float* __restrict__ W2, const float* __restrict__ b2,
    const float* __restrict__ W3, const float* __restrict__ b3,
    const float* __restrict__ wd, const float* __restrict__ bd,
    const float* __restrict__ wt, const float* __restrict__ bt,
    const float* __restrict__ wc, const float* __restrict__ bc,
    const float* __restrict__ h0,
    float* __restrict__ out, int T)
{
    __shared__ __align__(16) float ubuf[NBUF][CHUNK * UDIM];
    __shared__ __align__(16) float z1s[HID];
    __shared__ __align__(16) float z2s[HID];
    __shared__ __align__(16) float dus[HID];     // du(t), produced one step ahead by warp 2
    __shared__ __align__(16) double sumz2[HID];

    const int tid  = threadIdx.x;
    const int lane = tid & 31;
    const float dt = 5.0f / 60.0f;
    const int n_chunks = (T + CHUNK - 1) / CHUNK;

    const bool is_s  = (tid < HID);                      // warps 0,1
    const bool is_w2 = (tid >= HID);                     // warp 2: readouts + du helper
    const bool is_ro = is_w2 && (lane < 3);

    auto copy_chunk = [&](int cc) {
        if (cc >= n_chunks) return;
        const int t0 = cc * CHUNK;
        const int nf = min(CHUNK, T - t0) * UDIM;
        const float* src = U + t0 * UDIM;
        float* dst = ubuf[cc % NBUF];
        const int nv = nf >> 2;
        for (int i = tid; i < nv; i += NTHREADS) cp16(smem_u32(dst + 4 * i), src + 4 * i);
        for (int i = (nv << 2) + tid; i < nf; i += NTHREADS) cp4(smem_u32(dst + i), src + i);
    };
    copy_chunk(0); cp_commit();
    copy_chunk(1); cp_commit();
    copy_chunk(2); cp_commit();

    // ---------------- prologue (overlaps the in-flight cp.async) ----------------
    float A[HID], B[HID];
    float w1ua[UDIM], w1ub[UDIM];        // warp2: u-weights for neurons lane, lane+32
    float state = 0.0f, comp = 0.0f, cinit = 0.0f, b2r = 0.0f;
    float* outp = nullptr;
    double accz2 = 0.0;

    if (is_s) {
        const int n = tid;
        float w1h[HDIM];
        #pragma unroll
        for (int i = 0; i < HDIM; i++) w1h[i] = W1[n * XDIM + i];
        #pragma unroll
        for (int j = 0; j < HID; j++) B[j] = W2[n * HID + j];
        b2r = b2[n];
        // A = dt * (W1h @ W3) row n
        #pragma unroll 4
        for (int j = 0; j < HID; j++) {
            float m = 0.0f;
            #pragma unroll
            for (int i = 0; i < HDIM; i++) m = fmaf(w1h[i], W3[i * HID + j], m);
            A[j] = dt * m;
        }
        float cd = 0.0f;
        #pragma unroll
        for (int i = 0; i < HDIM; i++) cd = fmaf(w1h[i], b3[i], cd);
        cinit = dt * cd;
        // state seeded s0 - cinit so the uniform "+cinit" lands exactly at t=0 (z2s=0)
        float s0 = b1[n];
        #pragma unroll
        for (int i = 0; i < HDIM; i++) s0 = fmaf(w1h[i], h0[i], s0);
        state = s0 - cinit;
        z2s[n] = 0.0f;
    } else {
        // helper u-weights for neurons lane and lane+32
        #pragma unroll
        for (int i = 0; i < UDIM; i++) {
            w1ua[i] = W1[lane * XDIM + HDIM + i];
            w1ub[i] = W1[(lane + 32) * XDIM + HDIM + i];
        }
        #pragma unroll
        for (int j = 0; j < HID; j++) { A[j] = 0.0f; B[j] = 0.0f; }
        if (is_ro) {
            const int idx = lane;
            const float* wsel = (idx == 0) ? wd : (idx == 1) ? wt : wc;
            const float bsel  = (idx == 0) ? bd[0] : (idx == 1) ? bt[0] : bc[0];
            float ws[HDIM];
            #pragma unroll
            for (int i = 0; i < HDIM; i++) ws[i] = wsel[i];
            #pragma unroll 4
            for (int j = 0; j < HID; j++) {
                float m = 0.0f;
                #pragma unroll
                for (int i = 0; i < HDIM; i++) m = fmaf(ws[i], W3[i * HID + j], m);
                A[j] = dt * m;
            }
            float rc = 0.0f;
            #pragma unroll
            for (int i = 0; i < HDIM; i++) rc = fmaf(ws[i], b3[i], rc);
            cinit = dt * rc;
            float r0 = bsel;
            #pragma unroll
            for (int i = 0; i < HDIM; i++) r0 = fmaf(ws[i], h0[i], r0);
            state = r0 - cinit;
            outp = out + idx * T;
        }
    }

    // seed dus with du(0): needs chunk 0 resident
    cp_wait2();                                  // 3 committed -> oldest (chunk 0) done
    if (is_w2) {
        const float* up = ubuf[0];
        float u0 = up[0], u1 = up[1], u2 = up[2], u3 = up[3];
        float u4 = up[4], u5 = up[5], u6 = up[6];
        float d0 = w1ua[0] * u0;            float e0 = w1ub[0] * u0;
        d0 = fmaf(w1ua[1], u1, d0);         e0 = fmaf(w1ub[1], u1, e0);
        d0 = fmaf(w1ua[2], u2, d0);         e0 = fmaf(w1ub[2], u2, e0);
        d0 = fmaf(w1ua[3], u3, d0);         e0 = fmaf(w1ub[3], u3, e0);
        d0 = fmaf(w1ua[4], u4, d0);         e0 = fmaf(w1ub[4], u4, e0);
        d0 = fmaf(w1ua[5], u5, d0);         e0 = fmaf(w1ub[5], u5, e0);
        d0 = fmaf(w1ua[6], u6, d0);         e0 = fmaf(w1ub[6], u6, e0);
        dus[lane] = d0;
        dus[lane + 32] = e0;
    }

    // ---------------- main loop: 2 barriers per step ----------------
    for (int c = 0; c < n_chunks; c++) {
        cp_wait1();                              // chunks <= c+1 resident
        __syncthreads();                         // visibility of all threads' copies + dus/z2s
        const int nst = min(CHUNK, T - c * CHUNK);
        const int tbase = c * CHUNK;

        for (int k = 0; k < nst; k++) {
            // ======== window A: P1 on z2(t-1) ========
            if (is_s) {
                const float du = dus[tid];               // early LDS, latency hides under dot
                const float delta = dot64(A, z2s, cinit);
                const float y  = delta - comp;           // Kahan (identical math to R11)
                const float t2 = state + y;
                comp = (t2 - state) - y;
                state = t2;
                z1s[tid] = ftanh(t2 + du);
            } else if (is_ro) {
                const float delta = dot64(A, z2s, cinit);
                const float y  = delta - comp;
                const float t2 = state + y;
                comp = (t2 - state) - y;
                state = t2;
                outp[tbase + k] = state;                 // r(t) = wsel@h(t)+b
            }
            __syncthreads();                             // bar1: z1s ready, z2s/dus reads done

            // ======== window B: P2 -> z2(t); warp2 produces du(t+1) ========
            if (is_s) {
                const float z2 = ftanh(dot64(B, z1s, b2r));
                z2s[tid] = z2;
                accz2 += (double)z2;                     // exact hT reconstruction
            } else {
                const int t1 = tbase + k + 1;
                if (t1 < T) {
                    const float* up = ubuf[(t1 >> 9) % NBUF] + (t1 & (CHUNK - 1)) * UDIM;
                    float u0 = up[0], u1 = up[1], u2 = up[2], u3 = up[3];
                    float u4 = up[4], u5 = up[5], u6 = up[6];
                    float d0 = w1ua[0] * u0;            float e0 = w1ub[0] * u0;
                    d0 = fmaf(w1ua[1], u1, d0);         e0 = fmaf(w1ub[1], u1, e0);
                    d0 = fmaf(w1ua[2], u2, d0);         e0 = fmaf(w1ub[2], u2, e0);
                    d0 = fmaf(w1ua[3], u3, d0);         e0 = fmaf(w1ub[3], u3, e0);
                    d0 = fmaf(w1ua[4], u4, d0);         e0 = fmaf(w1ub[4], u4, e0);
                    d0 = fmaf(w1ua[5], u5, d0);         e0 = fmaf(w1ub[5], u5, e0);
                    d0 = fmaf(w1ua[6], u6, d0);         e0 = fmaf(w1ub[6], u6, e0);
                    dus[lane] = d0;
                    dus[lane + 32] = e0;
                }
            }
            __syncthreads();                             // bar2: z2s + dus(t+1) ready
        }
        copy_chunk(c + 3);
        cp_commit();
    }

    // ---------------- finalize hT = h0 + dt*(W3 @ sum(z2) + T*b3) in fp64 ----------------
    __syncthreads();
    if (is_s) sumz2[tid] = accz2;
    __syncthreads();
    if (tid < HDIM) {
        double acc = (double)T * (double)b3[tid];
        #pragma unroll 8
        for (int j = 0; j < HID; j++)
            acc += (double)W3[tid * HID + j] * sumz2[j];
        out[3 * T + tid] = (float)((double)h0[tid] + (double)dt * acc);
    }
}

extern "C" void kernel_launch(void* const* d_in, const int* in_sizes, int n_in,
                              void* d_out, int out_size)
{
    const int T = in_sizes[0] / UDIM;
    node_scan_kernel<<<1, NTHREADS>>>(
        (const float*)d_in[0],                          // U
        (const float*)d_in[1], (const float*)d_in[2],   // W1, b1
        (const float*)d_in[3], (const float*)d_in[4],   // W2, b2
        (const float*)d_in[5], (const float*)d_in[6],   // W3, b3
        (const float*)d_in[7], (const float*)d_in[8],   // wd, bd
        (const float*)d_in[9], (const float*)d_in[10],  // wt, bt
        (const float*)d_in[11], (const float*)d_in[12], // wc, bc
        (const float*)d_in[13],                         // h0
        (float*)d_out, T);
}

// round 14
// speedup vs baseline: 1.9625x; 1.9625x over previous
#include <cuda_runtime.h>
#include <cuda_bf16.h>

#define HDIM 16
#define UDIM 7
#define HID  64
#define XDIM 23
#define CHUNK 512
#define NTHREADS 64

typedef unsigned long long u64;

__device__ __forceinline__ unsigned smem_u32(const void* p) {
    return (unsigned)__cvta_generic_to_shared(p);
}
__device__ __forceinline__ void cp16(unsigned dst, const void* src) {
    asm volatile("cp.async.cg.shared.global [%0], [%1], 16;" :: "r"(dst), "l"(src));
}
__device__ __forceinline__ void cp4(unsigned dst, const void* src) {
    asm volatile("cp.async.ca.shared.global [%0], [%1], 4;" :: "r"(dst), "l"(src));
}
__device__ __forceinline__ void cp_commit() {
    asm volatile("cp.async.commit_group;" ::: "memory");
}
__device__ __forceinline__ void cp_wait1() {
    asm volatile("cp.async.wait_group 1;" ::: "memory");
}

// packed f32x2 helpers
__device__ __forceinline__ u64 pack2(float lo, float hi) {
    u64 r; asm("mov.b64 %0, {%1, %2};" : "=l"(r) : "f"(lo), "f"(hi)); return r;
}
__device__ __forceinline__ float2 unpack2(u64 v) {
    float2 f; asm("mov.b64 {%0, %1}, %2;" : "=f"(f.x), "=f"(f.y) : "l"(v)); return f;
}
__device__ __forceinline__ u64 fma2(u64 a, u64 b, u64 c) {
    u64 r; asm("fma.rn.f32x2 %0, %1, %2, %3;" : "=l"(r) : "l"(a), "l"(b), "l"(c)); return r;
}
__device__ __forceinline__ u64 add2(u64 a, u64 b) {
    u64 r; asm("add.rn.f32x2 %0, %1, %2;" : "=l"(r) : "l"(a), "l"(b)); return r;
}

// accurate tanh: (e^{2x}-1)/(e^{2x}+1), clamped to avoid inf/inf
__device__ __forceinline__ float ftanh(float x) {
    x = fminf(fmaxf(x, -15.0f), 15.0f);
    float e = __expf(2.0f * x);
    return __fdividef(e - 1.0f, e + 1.0f);
}

__global__ void __launch_bounds__(NTHREADS, 1) node_scan_kernel(
    const float* __restrict__ U,
    const float* __restrict__ W1, const float* __restrict__ b1,
    const float* __restrict__ W2, const float* __restrict__ b2,
    const float* __restrict__ W3, const float* __restrict__ b3,
    const float* __restrict__ wd, const float* __restrict__ bd,
    const float* __restrict__ wt, const float* __restrict__ bt,
    const float* __restrict__ wc, const float* __restrict__ bc,
    const float* __restrict__ h0,
    float* __restrict__ out, int T)
{
    __shared__ __align__(16) float ubuf[2][CHUNK * UDIM];
    __shared__ __align__(16) float hs[HDIM];
    __shared__ __align__(16) float z1s[HID];
    __shared__ __align__(16) float z2s[HID];

    const int tid  = threadIdx.x;
    const int lane = tid & 31;
    const float dt = 5.0f / 60.0f;
    const int n_chunks = (T + CHUNK - 1) / CHUNK;

    // ---- weights into registers (R0 layout, packed for f32x2 where used) ----
    float w1[XDIM];
    #pragma unroll
    for (int k = 0; k < XDIM; k++) w1[k] = W1[tid * XDIM + k];
    const float b1r = b1[tid];

    u64 w2p[32];                          // W2 row, packed pairs
    #pragma unroll
    for (int j = 0; j < 32; j++)
        w2p[j] = pack2(W2[tid * HID + 2 * j], W2[tid * HID + 2 * j + 1]);
    const u64 b2init = pack2(b2[tid], 0.0f);

    // phase-C half split inside warp 0: lane l -> output o=l&15, half=l>>4
    u64 w3p[16];
    float cini = 0.0f;
    if (tid < 32) {
        const int o = lane & 15;
        const int hb = (lane >> 4) * 32;   // z2 base of this half
        #pragma unroll
        for (int j = 0; j < 16; j++)
            w3p[j] = pack2(W3[o * HID + hb + 2 * j], W3[o * HID + hb + 2 * j + 1]);
        if (lane < 16) cini = b3[o];       // b3 folded into the low half's partial
    } else {
        #pragma unroll
        for (int j = 0; j < 16; j++) w3p[j] = 0ull;
    }

    // readout lanes: tid 32..34 (warp 1 lanes 0..2), registers only — as in R0
    float wr[HDIM];
    float br = 0.0f;
    float* outp = nullptr;
    if (tid == 32) {
        #pragma unroll
        for (int k = 0; k < HDIM; k++) wr[k] = wd[k];
        br = bd[0]; outp = out;
    } else if (tid == 33) {
        #pragma unroll
        for (int k = 0; k < HDIM; k++) wr[k] = wt[k];
        br = bt[0]; outp = out + T;
    } else if (tid == 34) {
        #pragma unroll
        for (int k = 0; k < HDIM; k++) wr[k] = wc[k];
        br = bc[0]; outp = out + 2 * T;
    } else {
        #pragma unroll
        for (int k = 0; k < HDIM; k++) wr[k] = 0.0f;
    }

    if (tid < HDIM) hs[tid] = h0[tid];

    auto copy_chunk = [&](int cc) {
        if (cc >= n_chunks) return;
        const int t0 = cc * CHUNK;
        const int nf = min(CHUNK, T - t0) * UDIM;
        const float* src = U + t0 * UDIM;
        float* dst = ubuf[cc & 1];
        const int nv = nf >> 2;
        for (int i = tid; i < nv; i += NTHREADS) cp16(smem_u32(dst + 4 * i), src + 4 * i);
        for (int i = (nv << 2) + tid; i < nf; i += NTHREADS) cp4(smem_u32(dst + i), src + i);
    };
    copy_chunk(0); cp_commit();
    copy_chunk(1); cp_commit();

    for (int c = 0; c < n_chunks; c++) {
        cp_wait1();
        __syncthreads();                   // chunk data visible; hs valid
        const int nst = min(CHUNK, T - c * CHUNK);
        const float* ub = ubuf[c & 1];

        for (int k = 0; k < nst; k++) {
            const int t = c * CHUNK + k;

            // ---- phase A: z1 = tanh(W1 @ [h,u] + b1); capture h in regs ----
            float h[HDIM];
            {
                const float4* h4 = (const float4*)hs;
                float4 ha = h4[0], hb = h4[1], hc = h4[2], hd = h4[3];
                h[0] = ha.x;  h[1] = ha.y;  h[2] = ha.z;  h[3] = ha.w;
                h[4] = hb.x;  h[5] = hb.y;  h[6] = hb.z;  h[7] = hb.w;
                h[8] = hc.x;  h[9] = hc.y;  h[10] = hc.z; h[11] = hc.w;
                h[12] = hd.x; h[13] = hd.y; h[14] = hd.z; h[15] = hd.w;
            }
            float a0 = b1r, a1 = 0.0f, a2 = 0.0f, a3 = 0.0f;
            #pragma unroll
            for (int j = 0; j < HDIM; j += 4) {
                a0 = fmaf(w1[j + 0], h[j + 0], a0);
                a1 = fmaf(w1[j + 1], h[j + 1], a1);
                a2 = fmaf(w1[j + 2], h[j + 2], a2);
                a3 = fmaf(w1[j + 3], h[j + 3], a3);
            }
            {
                const float* up = ub + k * UDIM;
                float u0 = up[0], u1 = up[1], u2 = up[2], u3 = up[3];
                float u4 = up[4], u5 = up[5], u6 = up[6];
                a0 = fmaf(w1[16], u0, a0);
                a1 = fmaf(w1[17], u1, a1);
                a2 = fmaf(w1[18], u2, a2);
                a3 = fmaf(w1[19], u3, a3);
                a0 = fmaf(w1[20], u4, a0);
                a1 = fmaf(w1[21], u5, a1);
                a2 = fmaf(w1[22], u6, a2);
            }
            z1s[tid] = ftanh((a0 + a1) + (a2 + a3));
            __syncthreads();               // bar1: z1s ready

            // ---- phase B: z2 = tanh(W2 @ z1 + b2), packed f32x2 dot ----
            {
                const ulonglong2* zp = (const ulonglong2*)z1s;
                u64 c0 = b2init, c1 = 0ull, c2 = 0ull, c3 = 0ull;
                #pragma unroll
                for (int j = 0; j < 8; j++) {
                    ulonglong2 q0 = zp[2 * j];
                    ulonglong2 q1 = zp[2 * j + 1];
                    c0 = fma2(w2p[4 * j + 0], q0.x, c0);
                    c1 = fma2(w2p[4 * j + 1], q0.y, c1);
                    c2 = fma2(w2p[4 * j + 2], q1.x, c2);
                    c3 = fma2(w2p[4 * j + 3], q1.y, c3);
                }
                c0 = add2(c0, c1);
                c2 = add2(c2, c3);
                c0 = add2(c0, c2);
                float2 f = unpack2(c0);
                z2s[tid] = ftanh(f.x + f.y);
            }
            __syncthreads();               // bar2: z2s ready

            // ---- phase C: warp0 half-split W3 dot + shfl; warp1 readouts ----
            if (tid < 32) {
                const int o  = lane & 15;
                const int hb = (lane >> 4) * 32;
                const ulonglong2* zp = (const ulonglong2*)(z2s + hb);
                u64 d0 = pack2(cini, 0.0f), d1 = 0ull, d2 = 0ull, d3 = 0ull;
                #pragma unroll
                for (int j = 0; j < 4; j++) {
                    ulonglong2 q0 = zp[2 * j];
                    ulonglong2 q1 = zp[2 * j + 1];
                    d0 = fma2(w3p[4 * j + 0], q0.x, d0);
                    d1 = fma2(w3p[4 * j + 1], q0.y, d1);
                    d2 = fma2(w3p[4 * j + 2], q1.x, d2);
                    d3 = fma2(w3p[4 * j + 3], q1.y, d3);
                }
                d0 = add2(d0, d1);
                d2 = add2(d2, d3);
                d0 = add2(d0, d2);
                float2 f = unpack2(d0);
                float p = f.x + f.y;                       // this half's partial (+b3 low)
                p += __shfl_xor_sync(0xffffffffu, p, 16);  // combine halves
                if (lane < 16) hs[o] = hs[o] + p * dt;     // h_{t+1}
            } else if (tid < 35) {
                float r = br;                              // readout on pre-update h
                #pragma unroll
                for (int j = 0; j < HDIM; j++) r = fmaf(wr[j], h[j], r);
                outp[t] = r;
            }
            __syncthreads();               // bar3: hs updated
        }

        copy_chunk(c + 2);
        cp_commit();
    }

    __syncthreads();
    if (tid < HDIM) out[3 * T + tid] = hs[tid];
}

extern "C" void kernel_launch(void* const* d_in, const int* in_sizes, int n_in,
                              void* d_out, int out_size)
{
    const int T = in_sizes[0] / UDIM;
    node_scan_kernel<<<1, NTHREADS>>>(
        (const float*)d_in[0],                          // U
        (const float*)d_in[1], (const float*)d_in[2],   // W1, b1
        (const float*)d_in[3], (const float*)d_in[4],   // W2, b2
        (const float*)d_in[5], (const float*)d_in[6],   // W3, b3
        (const float*)d_in[7], (const float*)d_in[8],   // wd, bd
        (const float*)d_in[9], (const float*)d_in[10],  // wt, bt
        (const float*)d_in[11], (const float*)d_in[12], // wc, bc
        (const float*)d_in[13],                         // h0
        (float*)d_out, T);
}